// round 1
// baseline (speedup 1.0000x reference)
#include <cuda_runtime.h>

// Problem constants (fixed shapes from reference)
#define N_NODES 8192
#define F_IN    256
#define D_OUT   64

#define BI 64      // rows per block (main kernel)
#define BJ 64      // j columns per tile
#define MAIN_THREADS 256
#define PS_STRIDE (BJ + 4)   // 68: padded row stride for P tile

// Scratch (device globals; no allocation allowed)
__device__ float g_h[N_NODES * D_OUT];   // h = x @ trans
__device__ float g_e1[N_NODES];
__device__ float g_e2[N_NODES];

// ---------------- packed f32x2 helpers (Blackwell FFMA2 path) ----------------
__device__ __forceinline__ unsigned long long pk2(float lo, float hi) {
    unsigned long long r;
    asm("mov.b64 %0, {%1, %2};" : "=l"(r) : "f"(lo), "f"(hi));
    return r;
}
__device__ __forceinline__ void upk2(float& lo, float& hi, unsigned long long v) {
    asm("mov.b64 {%0, %1}, %2;" : "=f"(lo), "=f"(hi) : "l"(v));
}
__device__ __forceinline__ void fma2(unsigned long long& d, unsigned long long a,
                                     unsigned long long b) {
    asm("fma.rn.f32x2 %0, %1, %2, %0;" : "+l"(d) : "l"(a), "l"(b));
}
__device__ __forceinline__ void add2(unsigned long long& d, unsigned long long a) {
    asm("add.rn.f32x2 %0, %0, %1;" : "+l"(d) : "l"(a));
}

// ---------------- kernel 1: h = x @ trans  (8192x256 @ 256x64) ----------------
// Block: 16 rows x 64 cols, 256 threads, each thread 4 rows x 1 col.
__global__ void k_h_gemm(const float* __restrict__ x,
                         const float* __restrict__ trans) {
    __shared__ float xs[16 * F_IN];     // 16 KB
    __shared__ float ts[64 * D_OUT];    // 16 KB (k-chunk of 64)

    const int t = threadIdx.x;
    const int d = t & 63;
    const int rg = t >> 6;              // 0..3 -> rows rg*4 .. rg*4+3
    const int ibase = blockIdx.x * 16;

    // load x tile (contiguous 16x256 floats)
    {
        const float4* xg4 = reinterpret_cast<const float4*>(x) + (size_t)ibase * (F_IN / 4);
        float4* xs4 = reinterpret_cast<float4*>(xs);
        #pragma unroll
        for (int q = 0; q < 4; q++) xs4[t + q * 256] = xg4[t + q * 256];
    }

    float acc[4] = {0.f, 0.f, 0.f, 0.f};

    for (int kc = 0; kc < 4; kc++) {
        // load trans chunk (contiguous 64x64 floats)
        {
            const float4* tg4 = reinterpret_cast<const float4*>(trans) + kc * 1024;
            float4* ts4 = reinterpret_cast<float4*>(ts);
            #pragma unroll
            for (int q = 0; q < 4; q++) ts4[t + q * 256] = tg4[t + q * 256];
        }
        __syncthreads();
        #pragma unroll 8
        for (int k = 0; k < 64; k++) {
            const float tv = ts[k * 64 + d];
            const int kk = kc * 64 + k;
            #pragma unroll
            for (int r = 0; r < 4; r++)
                acc[r] = fmaf(xs[(rg * 4 + r) * F_IN + kk], tv, acc[r]);
        }
        __syncthreads();
    }

    #pragma unroll
    for (int r = 0; r < 4; r++)
        g_h[(size_t)(ibase + rg * 4 + r) * D_OUT + d] = acc[r];
}

// ---------------- kernel 2: e1/e2 = h @ attn halves ----------------
// one warp per row
__global__ void k_e(const float* __restrict__ attn) {
    const int wid = threadIdx.x >> 5;
    const int lane = threadIdx.x & 31;
    const int row = blockIdx.x * 8 + wid;

    const float h0 = g_h[(size_t)row * D_OUT + lane];
    const float h1 = g_h[(size_t)row * D_OUT + lane + 32];
    float v1 = h0 * attn[lane] + h1 * attn[lane + 32];
    float v2 = h0 * attn[64 + lane] + h1 * attn[96 + lane];
    #pragma unroll
    for (int o = 16; o > 0; o >>= 1) {
        v1 += __shfl_xor_sync(0xffffffffu, v1, o);
        v2 += __shfl_xor_sync(0xffffffffu, v2, o);
    }
    if (lane == 0) { g_e1[row] = v1; g_e2[row] = v2; }
}

// ---------------- kernel 3: fused masked-softmax @ h ----------------
__global__ __launch_bounds__(MAIN_THREADS, 1)
void k_attn(const int* __restrict__ mask, float* __restrict__ out) {
    __shared__ float Ps[BI * PS_STRIDE];   // P tile, row-major [i][j], stride 68
    __shared__ float Hs[BJ * D_OUT];       // h tile, [j][d]
    __shared__ float e1s[BI];

    const int t = threadIdx.x;
    const int ibase = blockIdx.x * BI;

    // phase-A element mapping: e4 = t + 256*r4 ; il = e4>>4 ; j0 = (e4&15)*4
    const int ilb = t >> 4;            // base row within block
    const int j0 = (t & 15) << 2;      // base j within tile (quad)
    // FMA-phase mapping
    const int rowg = t >> 4;           // 0..15 -> rows rowg*4..+3
    const int colg = t & 15;           // 0..15 -> cols colg*4..+3

    if (t < BI) e1s[t] = g_e1[ibase + t];

    const int NTILES = N_NODES / BJ;   // 128

    // prologue prefetch (tile 0): mask + h tile
    int4 mreg[4];
    float4 hreg[4];
    {
        #pragma unroll
        for (int r4 = 0; r4 < 4; r4++) {
            const int il = ilb + 16 * r4;
            mreg[r4] = *reinterpret_cast<const int4*>(
                mask + (size_t)(ibase + il) * N_NODES + 0 + j0);
        }
        const float4* hg4 = reinterpret_cast<const float4*>(g_h);
        #pragma unroll
        for (int q = 0; q < 4; q++) hreg[q] = hg4[t + q * 256];   // tile 0: jbase=0
    }
    __syncthreads();

    unsigned long long cacc[4][2];
    unsigned long long zacc[4];
    #pragma unroll
    for (int r = 0; r < 4; r++) { cacc[r][0] = 0ull; cacc[r][1] = 0ull; zacc[r] = 0ull; }

    for (int tile = 0; tile < NTILES; tile++) {
        const int jbase = tile * BJ;

        // ---- Phase A: build P tile + stage h tile ----
        #pragma unroll
        for (int r4 = 0; r4 < 4; r4++) {
            const int il = ilb + 16 * r4;
            const float ei = e1s[il];
            const float4 e2v = *reinterpret_cast<const float4*>(g_e2 + jbase + j0);
            const int4 mm = mreg[r4];
            float4 p;
            {
                float s;
                s = ei + e2v.x; s = fmaxf(s, 0.2f * s); p.x = mm.x ? __expf(s) : 0.f;
                s = ei + e2v.y; s = fmaxf(s, 0.2f * s); p.y = mm.y ? __expf(s) : 0.f;
                s = ei + e2v.z; s = fmaxf(s, 0.2f * s); p.z = mm.z ? __expf(s) : 0.f;
                s = ei + e2v.w; s = fmaxf(s, 0.2f * s); p.w = mm.w ? __expf(s) : 0.f;
            }
            *reinterpret_cast<float4*>(&Ps[il * PS_STRIDE + j0]) = p;
        }
        {
            float4* hs4 = reinterpret_cast<float4*>(Hs);
            #pragma unroll
            for (int q = 0; q < 4; q++) hs4[t + q * 256] = hreg[q];
        }

        // ---- prefetch next tile (wrap to keep addresses valid) ----
        {
            const int nt = (tile + 1 < NTILES) ? tile + 1 : 0;
            const int jb2 = nt * BJ;
            #pragma unroll
            for (int r4 = 0; r4 < 4; r4++) {
                const int il = ilb + 16 * r4;
                mreg[r4] = *reinterpret_cast<const int4*>(
                    mask + (size_t)(ibase + il) * N_NODES + jb2 + j0);
            }
            const float4* hg4 = reinterpret_cast<const float4*>(g_h) + (size_t)jb2 * (D_OUT / 4);
            #pragma unroll
            for (int q = 0; q < 4; q++) hreg[q] = hg4[t + q * 256];
        }

        __syncthreads();

        // ---- FMA phase: C += P_tile @ H_tile, Z += row sums ----
        #pragma unroll 4
        for (int j = 0; j < BJ; j += 2) {
            const float4 ha = *reinterpret_cast<const float4*>(&Hs[j * D_OUT + colg * 4]);
            const float4 hb = *reinterpret_cast<const float4*>(&Hs[(j + 1) * D_OUT + colg * 4]);
            const unsigned long long ha01 = pk2(ha.x, ha.y);
            const unsigned long long ha23 = pk2(ha.z, ha.w);
            const unsigned long long hb01 = pk2(hb.x, hb.y);
            const unsigned long long hb23 = pk2(hb.z, hb.w);
            #pragma unroll
            for (int r = 0; r < 4; r++) {
                const unsigned long long p2 = *reinterpret_cast<const unsigned long long*>(
                    &Ps[(rowg * 4 + r) * PS_STRIDE + j]);
                add2(zacc[r], p2);
                float plo, phi;
                upk2(plo, phi, p2);
                const unsigned long long pl2 = pk2(plo, plo);
                const unsigned long long ph2 = pk2(phi, phi);
                fma2(cacc[r][0], pl2, ha01);
                fma2(cacc[r][1], pl2, ha23);
                fma2(cacc[r][0], ph2, hb01);
                fma2(cacc[r][1], ph2, hb23);
            }
        }
        __syncthreads();
    }

    // ---- epilogue: normalize and store ----
    #pragma unroll
    for (int r = 0; r < 4; r++) {
        float zlo, zhi;
        upk2(zlo, zhi, zacc[r]);
        const float rz = 1.0f / (zlo + zhi);
        float c0, c1, c2, c3;
        upk2(c0, c1, cacc[r][0]);
        upk2(c2, c3, cacc[r][1]);
        float4 o;
        o.x = c0 * rz; o.y = c1 * rz; o.z = c2 * rz; o.w = c3 * rz;
        *reinterpret_cast<float4*>(
            out + (size_t)(ibase + rowg * 4 + r) * D_OUT + colg * 4) = o;
    }
}

// ---------------- launch ----------------
extern "C" void kernel_launch(void* const* d_in, const int* in_sizes, int n_in,
                              void* d_out, int out_size) {
    const float* x     = (const float*)d_in[0];   // [8192, 256]
    const int*   mask  = (const int*)d_in[1];     // [8192, 8192]
    const float* trans = (const float*)d_in[2];   // [256, 64]
    const float* attn  = (const float*)d_in[3];   // [128, 1]
    float* out = (float*)d_out;                   // [8192, 64]

    k_h_gemm<<<N_NODES / 16, 256>>>(x, trans);
    k_e<<<N_NODES / 8, 256>>>(attn);
    k_attn<<<N_NODES / BI, MAIN_THREADS>>>(mask, out);
}

// round 3
// speedup vs baseline: 2.6489x; 2.6489x over previous
#include <cuda_runtime.h>
#include <cuda_bf16.h>
#include <cstdint>

// ---------------- problem constants ----------------
#define N_NODES 8192
#define F_IN    256
#define D_OUT   64

// ---------------- device scratch (no allocation allowed) ----------------
__device__ float g_h[N_NODES * D_OUT];
__device__ float g_e1[N_NODES];
__device__ float g_e2[N_NODES];
__device__ __nv_bfloat16 g_ht_hi[D_OUT * N_NODES];   // H^T hi split, [d][j]
__device__ __nv_bfloat16 g_ht_lo[D_OUT * N_NODES];   // H^T lo split
__device__ float g_po[2 * N_NODES * D_OUT];          // partial O per j-half
__device__ float g_pz[2 * N_NODES];                  // partial Z per j-half

// ---------------- helpers ----------------
__device__ __forceinline__ uint32_t smem_u32(const void* p) {
    uint32_t a;
    asm("{ .reg .u64 t; cvta.to.shared.u64 t, %1; cvt.u32.u64 %0, t; }"
        : "=r"(a) : "l"(p));
    return a;
}
__device__ __forceinline__ uint32_t pack_bf16x2(float lo, float hi) {
    uint32_t r;
    asm("cvt.rn.bf16x2.f32 %0, %1, %2;" : "=r"(r) : "f"(hi), "f"(lo));
    return r;
}
__device__ __forceinline__ void ldsm_x4(uint32_t (&r)[4], uint32_t addr) {
    asm volatile("ldmatrix.sync.aligned.m8n8.x4.shared.b16 {%0,%1,%2,%3}, [%4];"
                 : "=r"(r[0]), "=r"(r[1]), "=r"(r[2]), "=r"(r[3]) : "r"(addr));
}
__device__ __forceinline__ void mma16816(float (&c)[4], const uint32_t (&a)[4],
                                         const uint32_t* b) {
    asm volatile("mma.sync.aligned.m16n8k16.row.col.f32.bf16.bf16.f32 "
        "{%0,%1,%2,%3}, {%4,%5,%6,%7}, {%8,%9}, {%0,%1,%2,%3};"
        : "+f"(c[0]), "+f"(c[1]), "+f"(c[2]), "+f"(c[3])
        : "r"(a[0]), "r"(a[1]), "r"(a[2]), "r"(a[3]), "r"(b[0]), "r"(b[1]));
}

// ---------------- kernel 1: h = x @ trans, fused bf16 split transpose ----------------
__global__ void k_h_gemm(const float* __restrict__ x,
                         const float* __restrict__ trans) {
    __shared__ float xs[16 * F_IN];
    __shared__ float ts[64 * D_OUT];
    __shared__ float trs[64 * 17];

    const int t = threadIdx.x;
    const int d = t & 63;
    const int rg = t >> 6;
    const int ibase = blockIdx.x * 16;

    {
        const float4* xg4 = reinterpret_cast<const float4*>(x) + (size_t)ibase * (F_IN / 4);
        float4* xs4 = reinterpret_cast<float4*>(xs);
        #pragma unroll
        for (int q = 0; q < 4; q++) xs4[t + q * 256] = xg4[t + q * 256];
    }

    float acc[4] = {0.f, 0.f, 0.f, 0.f};

    for (int kc = 0; kc < 4; kc++) {
        {
            const float4* tg4 = reinterpret_cast<const float4*>(trans) + kc * 1024;
            float4* ts4 = reinterpret_cast<float4*>(ts);
            #pragma unroll
            for (int q = 0; q < 4; q++) ts4[t + q * 256] = tg4[t + q * 256];
        }
        __syncthreads();
        #pragma unroll 8
        for (int k = 0; k < 64; k++) {
            const float tv = ts[k * 64 + d];
            const int kk = kc * 64 + k;
            #pragma unroll
            for (int r = 0; r < 4; r++)
                acc[r] = fmaf(xs[(rg * 4 + r) * F_IN + kk], tv, acc[r]);
        }
        __syncthreads();
    }

    #pragma unroll
    for (int r = 0; r < 4; r++) {
        g_h[(size_t)(ibase + rg * 4 + r) * D_OUT + d] = acc[r];
        trs[d * 17 + rg * 4 + r] = acc[r];
    }
    __syncthreads();

    {
        const int dd = t >> 2;
        const int seg = t & 3;
        float v0 = trs[dd * 17 + seg * 4 + 0];
        float v1 = trs[dd * 17 + seg * 4 + 1];
        float v2 = trs[dd * 17 + seg * 4 + 2];
        float v3 = trs[dd * 17 + seg * 4 + 3];
        uint32_t h01 = pack_bf16x2(v0, v1);
        uint32_t h23 = pack_bf16x2(v2, v3);
        float f0 = __uint_as_float(h01 << 16);
        float f1 = __uint_as_float(h01 & 0xffff0000u);
        float f2 = __uint_as_float(h23 << 16);
        float f3 = __uint_as_float(h23 & 0xffff0000u);
        uint32_t l01 = pack_bf16x2(v0 - f0, v1 - f1);
        uint32_t l23 = pack_bf16x2(v2 - f2, v3 - f3);
        const size_t off = (size_t)dd * N_NODES + ibase + seg * 4;
        *reinterpret_cast<uint2*>(g_ht_hi + off) = make_uint2(h01, h23);
        *reinterpret_cast<uint2*>(g_ht_lo + off) = make_uint2(l01, l23);
    }
}

// ---------------- kernel 2: e1/e2 projections ----------------
__global__ void k_e(const float* __restrict__ attn) {
    const int wid = threadIdx.x >> 5;
    const int lane = threadIdx.x & 31;
    const int row = blockIdx.x * 8 + wid;

    const float h0 = g_h[(size_t)row * D_OUT + lane];
    const float h1 = g_h[(size_t)row * D_OUT + lane + 32];
    float v1 = h0 * attn[lane] + h1 * attn[lane + 32];
    float v2 = h0 * attn[64 + lane] + h1 * attn[96 + lane];
    #pragma unroll
    for (int o = 16; o > 0; o >>= 1) {
        v1 += __shfl_xor_sync(0xffffffffu, v1, o);
        v2 += __shfl_xor_sync(0xffffffffu, v2, o);
    }
    if (lane == 0) { g_e1[row] = v1; g_e2[row] = v2; }
}

// ---------------- kernel 3: fused masked exp + mma.sync P@H ----------------
// SMEM byte offsets from 128-aligned base.
// P tiles: 128 rows x 64 bf16, row stride 144B (16B pad, conflict-free ldmatrix)
// H tiles: 64 rows (d) x 64 bf16 (j), row stride 144B
#define PROW 144
#define PHI_OFF(b) ((b) * 18432)               // 2 x 18KB
#define PLO_OFF(b) (36864 + (b) * 18432)       // 2 x 18KB
#define BHI_OFF(b) (73728 + (b) * 9216)        // 2 x 9KB
#define BLO_OFF(b) (92160 + (b) * 9216)        // 2 x 9KB
#define E2S_OFF    110592                      // 16KB
#define SMEM_BYTES (110592 + 16384 + 128)

#define NT_HALF 64   // 4096 / 64 tiles per CTA

__global__ __launch_bounds__(512, 1)
void k_attn_mma(const int* __restrict__ mask) {
    extern __shared__ char dsmem[];
    __shared__ float zs[128];

    const int t = threadIdx.x;
    const int lane = t & 31;
    const int w = t >> 5;
    const int half = blockIdx.x >> 6;
    const int ibase = (blockIdx.x & 63) * 128;
    const int jbase0 = half * 4096;

    const uint32_t sbase = smem_u32(dsmem);
    const uint32_t abase = (sbase + 127) & ~127u;
    char* ab = dsmem + (abase - sbase);

    // stage e2 half-range into SMEM (16KB)
    {
        float4* dst = reinterpret_cast<float4*>(ab + E2S_OFF);
        const float4* src = reinterpret_cast<const float4*>(g_e2 + jbase0);
        dst[t] = src[t];
        dst[t + 512] = src[t + 512];
    }
    const float* e2s = reinterpret_cast<const float*>(ab + E2S_OFF);

    // phase-A mapping: one row, 16 consecutive j per thread
    const int il = t >> 2;
    const int q = t & 3;
    const int j0 = q * 16;
    const int gi = ibase + il;
    const float ei = g_e1[gi];
    // H staging mapping: one 16B chunk per thread
    const int bd = t >> 3;
    const int bc = t & 7;

    const uint4* mbase = reinterpret_cast<const uint4*>(
        mask + (size_t)gi * N_NODES + jbase0 + j0);
    const __nv_bfloat16* bhbase = g_ht_hi + (size_t)bd * N_NODES + jbase0 + bc * 8;
    const __nv_bfloat16* blbase = g_ht_lo + (size_t)bd * N_NODES + jbase0 + bc * 8;

    // MMA mapping: warp w -> rows (w&7)*16, cols (w>>3)*32
    const int arow = (w & 7) * 16;
    const int ncol = (w >> 3) * 32;
    const uint32_t a_off = (uint32_t)((arow + (lane & 15)) * PROW + ((lane >> 4) << 4));
    const uint32_t b_row0 = (uint32_t)(ncol + ((lane >> 4) << 3) + (lane & 7));
    const uint32_t b_byte = (uint32_t)(((lane >> 3) & 1) << 4);
    const uint32_t b_off  = b_row0 * PROW + b_byte;
    const uint32_t b_off2 = (b_row0 + 16) * PROW + b_byte;

    // prefetch tile 0
    uint4 m0 = mbase[0], m1 = mbase[1], m2 = mbase[2], m3 = mbase[3];
    uint4 bh = *reinterpret_cast<const uint4*>(bhbase);
    uint4 bl = *reinterpret_cast<const uint4*>(blbase);

    float zpart = 0.f;
    float acc[4][4];
    #pragma unroll
    for (int n = 0; n < 4; n++)
        #pragma unroll
        for (int c = 0; c < 4; c++) acc[n][c] = 0.f;

    __syncthreads();   // e2s visible

    for (int tile = 0; tile < NT_HALF; tile++) {
        const int buf = tile & 1;

        // ---- stage H tile (hi/lo) ----
        {
            const uint32_t so = (uint32_t)(bd * PROW + bc * 16);
            *reinterpret_cast<uint4*>(ab + BHI_OFF(buf) + so) = bh;
            *reinterpret_cast<uint4*>(ab + BLO_OFF(buf) + so) = bl;
        }

        // ---- compute P tile, split bf16 hi/lo ----
        {
            const float* e2p = e2s + tile * 64 + j0;
            const float4 ea = reinterpret_cast<const float4*>(e2p)[0];
            const float4 eb = reinterpret_cast<const float4*>(e2p)[1];
            const float4 ec = reinterpret_cast<const float4*>(e2p)[2];
            const float4 ed = reinterpret_cast<const float4*>(e2p)[3];
            const float e2a[16] = {ea.x, ea.y, ea.z, ea.w, eb.x, eb.y, eb.z, eb.w,
                                   ec.x, ec.y, ec.z, ec.w, ed.x, ed.y, ed.z, ed.w};
            const uint32_t ma[16] = {m0.x, m0.y, m0.z, m0.w, m1.x, m1.y, m1.z, m1.w,
                                     m2.x, m2.y, m2.z, m2.w, m3.x, m3.y, m3.z, m3.w};
            uint32_t hiu[8], lou[8];
            #pragma unroll
            for (int kk = 0; kk < 8; kk++) {
                float s0 = ei + e2a[2 * kk];
                float s1 = ei + e2a[2 * kk + 1];
                s0 = fmaxf(s0, 0.2f * s0);
                s1 = fmaxf(s1, 0.2f * s1);
                const float p0 = ma[2 * kk]     ? __expf(s0) : 0.f;
                const float p1 = ma[2 * kk + 1] ? __expf(s1) : 0.f;
                zpart += p0 + p1;
                const uint32_t uh = pack_bf16x2(p0, p1);
                const float f0 = __uint_as_float(uh << 16);
                const float f1 = __uint_as_float(uh & 0xffff0000u);
                hiu[kk] = uh;
                lou[kk] = pack_bf16x2(p0 - f0, p1 - f1);
            }
            const uint32_t ro = (uint32_t)(il * PROW + q * 32);
            *reinterpret_cast<uint4*>(ab + PHI_OFF(buf) + ro) =
                make_uint4(hiu[0], hiu[1], hiu[2], hiu[3]);
            *reinterpret_cast<uint4*>(ab + PHI_OFF(buf) + ro + 16) =
                make_uint4(hiu[4], hiu[5], hiu[6], hiu[7]);
            *reinterpret_cast<uint4*>(ab + PLO_OFF(buf) + ro) =
                make_uint4(lou[0], lou[1], lou[2], lou[3]);
            *reinterpret_cast<uint4*>(ab + PLO_OFF(buf) + ro + 16) =
                make_uint4(lou[4], lou[5], lou[6], lou[7]);
        }

        // ---- prefetch next tile (wrap keeps addresses valid) ----
        {
            const int nt = (tile + 1 < NT_HALF) ? tile + 1 : 0;
            const uint4* mp = mbase + nt * 16;
            m0 = mp[0]; m1 = mp[1]; m2 = mp[2]; m3 = mp[3];
            bh = *reinterpret_cast<const uint4*>(bhbase + nt * 64);
            bl = *reinterpret_cast<const uint4*>(blbase + nt * 64);
        }

        __syncthreads();

        // ---- MMA phase: 4 k-steps x (ldsm + 12 HMMA) ----
        const uint32_t phi = abase + PHI_OFF(buf);
        const uint32_t plo = abase + PLO_OFF(buf);
        const uint32_t bhi = abase + BHI_OFF(buf);
        const uint32_t blo = abase + BLO_OFF(buf);
        #pragma unroll
        for (int kk = 0; kk < 4; kk++) {
            uint32_t ahi[4], alo[4], bh0[4], bh1[4], bl0[4], bl1[4];
            ldsm_x4(ahi, phi + a_off + kk * 32);
            ldsm_x4(alo, plo + a_off + kk * 32);
            ldsm_x4(bh0, bhi + b_off + kk * 32);
            ldsm_x4(bh1, bhi + b_off2 + kk * 32);
            ldsm_x4(bl0, blo + b_off + kk * 32);
            ldsm_x4(bl1, blo + b_off2 + kk * 32);
            mma16816(acc[0], ahi, &bh0[0]);
            mma16816(acc[1], ahi, &bh0[2]);
            mma16816(acc[2], ahi, &bh1[0]);
            mma16816(acc[3], ahi, &bh1[2]);
            mma16816(acc[0], alo, &bh0[0]);
            mma16816(acc[1], alo, &bh0[2]);
            mma16816(acc[2], alo, &bh1[0]);
            mma16816(acc[3], alo, &bh1[2]);
            mma16816(acc[0], ahi, &bl0[0]);
            mma16816(acc[1], ahi, &bl0[2]);
            mma16816(acc[2], ahi, &bl1[0]);
            mma16816(acc[3], ahi, &bl1[2]);
        }
    }

    // ---- epilogue ----
    zpart += __shfl_xor_sync(0xffffffffu, zpart, 1);
    zpart += __shfl_xor_sync(0xffffffffu, zpart, 2);
    if (q == 0) zs[il] = zpart;

    // write partial O (per-warp registers; no barrier needed for O)
    {
        const int crow = arow + (lane >> 2);
        const int ccol = ncol + 2 * (lane & 3);
        float* po = g_po + (size_t)half * (N_NODES * D_OUT);
        #pragma unroll
        for (int n = 0; n < 4; n++) {
            *reinterpret_cast<float2*>(
                po + (size_t)(ibase + crow) * D_OUT + ccol + n * 8) =
                make_float2(acc[n][0], acc[n][1]);
            *reinterpret_cast<float2*>(
                po + (size_t)(ibase + crow + 8) * D_OUT + ccol + n * 8) =
                make_float2(acc[n][2], acc[n][3]);
        }
    }

    __syncthreads();
    if (t < 128) g_pz[half * N_NODES + ibase + t] = zs[t];
}

// ---------------- kernel 4: combine the two j-halves ----------------
__global__ void k_combine(float* __restrict__ out) {
    const int idx = blockIdx.x * 256 + threadIdx.x;   // over 8192*16 float4s
    const int i = idx >> 4;
    const float4 a = reinterpret_cast<const float4*>(g_po)[idx];
    const float4 b = reinterpret_cast<const float4*>(g_po)[idx + (N_NODES * D_OUT / 4)];
    const float rz = 1.0f / (g_pz[i] + g_pz[N_NODES + i]);
    float4 o;
    o.x = (a.x + b.x) * rz;
    o.y = (a.y + b.y) * rz;
    o.z = (a.z + b.z) * rz;
    o.w = (a.w + b.w) * rz;
    reinterpret_cast<float4*>(out)[idx] = o;
}

// ---------------- launch ----------------
extern "C" void kernel_launch(void* const* d_in, const int* in_sizes, int n_in,
                              void* d_out, int out_size) {
    const float* x     = (const float*)d_in[0];   // [8192, 256]
    const int*   mask  = (const int*)d_in[1];     // [8192, 8192]
    const float* trans = (const float*)d_in[2];   // [256, 64]
    const float* attn  = (const float*)d_in[3];   // [128, 1]
    float* out = (float*)d_out;                   // [8192, 64]

    cudaFuncSetAttribute(k_attn_mma, cudaFuncAttributeMaxDynamicSharedMemorySize,
                         SMEM_BYTES);

    k_h_gemm<<<N_NODES / 16, 256>>>(x, trans);
    k_e<<<N_NODES / 8, 256>>>(attn);
    k_attn_mma<<<128, 512, SMEM_BYTES>>>(mask);
    k_combine<<<(N_NODES * D_OUT / 4) / 256, 256>>>(out);
}

// round 4
// speedup vs baseline: 2.8626x; 1.0807x over previous
#include <cuda_runtime.h>
#include <cuda_bf16.h>
#include <cstdint>

// ---------------- problem constants ----------------
#define N_NODES 8192
#define F_IN    256
#define D_OUT   64
#define LOG2E   1.4426950408889634f

// ---------------- device scratch (no allocation allowed) ----------------
__device__ float g_h[N_NODES * D_OUT];
__device__ float g_e1[N_NODES];
__device__ float g_e2[N_NODES];
__device__ __nv_bfloat16 g_ht_hi[D_OUT * N_NODES];   // H^T hi split, [d][j]
__device__ __nv_bfloat16 g_ht_lo[D_OUT * N_NODES];   // H^T lo split
__device__ float g_po[2 * N_NODES * D_OUT];          // partial O per j-half
__device__ float g_pz[2 * N_NODES];                  // partial Z per j-half

// ---------------- helpers ----------------
__device__ __forceinline__ uint32_t smem_u32(const void* p) {
    uint32_t a;
    asm("{ .reg .u64 t; cvta.to.shared.u64 t, %1; cvt.u32.u64 %0, t; }"
        : "=r"(a) : "l"(p));
    return a;
}
__device__ __forceinline__ uint32_t pack_bf16x2(float lo, float hi) {
    uint32_t r;
    asm("cvt.rn.bf16x2.f32 %0, %1, %2;" : "=r"(r) : "f"(hi), "f"(lo));
    return r;
}
__device__ __forceinline__ float ex2(float x) {
    float r;
    asm("ex2.approx.ftz.f32 %0, %1;" : "=f"(r) : "f"(x));
    return r;
}
__device__ __forceinline__ unsigned long long pk2(float lo, float hi) {
    unsigned long long r;
    asm("mov.b64 %0, {%1, %2};" : "=l"(r) : "f"(lo), "f"(hi));
    return r;
}
__device__ __forceinline__ void upk2(float& lo, float& hi, unsigned long long v) {
    asm("mov.b64 {%0, %1}, %2;" : "=f"(lo), "=f"(hi) : "l"(v));
}
__device__ __forceinline__ void add2(unsigned long long& d, unsigned long long a) {
    asm("add.rn.f32x2 %0, %0, %1;" : "+l"(d) : "l"(a));
}
__device__ __forceinline__ void ldsm_x4(uint32_t (&r)[4], uint32_t addr) {
    asm volatile("ldmatrix.sync.aligned.m8n8.x4.shared.b16 {%0,%1,%2,%3}, [%4];"
                 : "=r"(r[0]), "=r"(r[1]), "=r"(r[2]), "=r"(r[3]) : "r"(addr));
}
__device__ __forceinline__ void mma16816(float (&c)[4], const uint32_t (&a)[4],
                                         const uint32_t* b) {
    asm volatile("mma.sync.aligned.m16n8k16.row.col.f32.bf16.bf16.f32 "
        "{%0,%1,%2,%3}, {%4,%5,%6,%7}, {%8,%9}, {%0,%1,%2,%3};"
        : "+f"(c[0]), "+f"(c[1]), "+f"(c[2]), "+f"(c[3])
        : "r"(a[0]), "r"(a[1]), "r"(a[2]), "r"(a[3]), "r"(b[0]), "r"(b[1]));
}

// ---------------- kernel 1: h = x @ trans, fused bf16 split transpose ----------------
__global__ void k_h_gemm(const float* __restrict__ x,
                         const float* __restrict__ trans) {
    __shared__ float xs[16 * F_IN];
    __shared__ float ts[64 * D_OUT];
    __shared__ float trs[64 * 17];

    const int t = threadIdx.x;
    const int d = t & 63;
    const int rg = t >> 6;
    const int ibase = blockIdx.x * 16;

    {
        const float4* xg4 = reinterpret_cast<const float4*>(x) + (size_t)ibase * (F_IN / 4);
        float4* xs4 = reinterpret_cast<float4*>(xs);
        #pragma unroll
        for (int q = 0; q < 4; q++) xs4[t + q * 256] = xg4[t + q * 256];
    }

    float acc[4] = {0.f, 0.f, 0.f, 0.f};

    for (int kc = 0; kc < 4; kc++) {
        {
            const float4* tg4 = reinterpret_cast<const float4*>(trans) + kc * 1024;
            float4* ts4 = reinterpret_cast<float4*>(ts);
            #pragma unroll
            for (int q = 0; q < 4; q++) ts4[t + q * 256] = tg4[t + q * 256];
        }
        __syncthreads();
        #pragma unroll 8
        for (int k = 0; k < 64; k++) {
            const float tv = ts[k * 64 + d];
            const int kk = kc * 64 + k;
            #pragma unroll
            for (int r = 0; r < 4; r++)
                acc[r] = fmaf(xs[(rg * 4 + r) * F_IN + kk], tv, acc[r]);
        }
        __syncthreads();
    }

    #pragma unroll
    for (int r = 0; r < 4; r++) {
        g_h[(size_t)(ibase + rg * 4 + r) * D_OUT + d] = acc[r];
        trs[d * 17 + rg * 4 + r] = acc[r];
    }
    __syncthreads();

    {
        const int dd = t >> 2;
        const int seg = t & 3;
        float v0 = trs[dd * 17 + seg * 4 + 0];
        float v1 = trs[dd * 17 + seg * 4 + 1];
        float v2 = trs[dd * 17 + seg * 4 + 2];
        float v3 = trs[dd * 17 + seg * 4 + 3];
        uint32_t h01 = pack_bf16x2(v0, v1);
        uint32_t h23 = pack_bf16x2(v2, v3);
        float f0 = __uint_as_float(h01 << 16);
        float f1 = __uint_as_float(h01 & 0xffff0000u);
        float f2 = __uint_as_float(h23 << 16);
        float f3 = __uint_as_float(h23 & 0xffff0000u);
        uint32_t l01 = pack_bf16x2(v0 - f0, v1 - f1);
        uint32_t l23 = pack_bf16x2(v2 - f2, v3 - f3);
        const size_t off = (size_t)dd * N_NODES + ibase + seg * 4;
        *reinterpret_cast<uint2*>(g_ht_hi + off) = make_uint2(h01, h23);
        *reinterpret_cast<uint2*>(g_ht_lo + off) = make_uint2(l01, l23);
    }
}

// ---------------- kernel 2: e1/e2 projections ----------------
__global__ void k_e(const float* __restrict__ attn) {
    const int wid = threadIdx.x >> 5;
    const int lane = threadIdx.x & 31;
    const int row = blockIdx.x * 8 + wid;

    const float h0 = g_h[(size_t)row * D_OUT + lane];
    const float h1 = g_h[(size_t)row * D_OUT + lane + 32];
    float v1 = h0 * attn[lane] + h1 * attn[lane + 32];
    float v2 = h0 * attn[64 + lane] + h1 * attn[96 + lane];
    #pragma unroll
    for (int o = 16; o > 0; o >>= 1) {
        v1 += __shfl_xor_sync(0xffffffffu, v1, o);
        v2 += __shfl_xor_sync(0xffffffffu, v2, o);
    }
    if (lane == 0) { g_e1[row] = v1; g_e2[row] = v2; }
}

// ---------------- kernel 3: warp-specialized masked exp + mma.sync P@H ----------------
#define PROW 144
#define PHI_OFF(b) ((b) * 18432)               // 2 x 18KB
#define PLO_OFF(b) (36864 + (b) * 18432)       // 2 x 18KB
#define BHI_OFF(b) (73728 + (b) * 9216)        // 2 x 9KB
#define BLO_OFF(b) (92160 + (b) * 9216)        // 2 x 9KB
#define E2S_OFF    110592                      // 16KB (prescaled by log2e)
#define SMEM_BYTES (110592 + 16384 + 128)

#define NT_HALF 64   // 4096 / 64 tiles per CTA

__global__ __launch_bounds__(512, 1)
void k_attn_ws(const int* __restrict__ mask) {
    extern __shared__ char dsmem[];
    __shared__ float zs[128];

    const int t = threadIdx.x;
    const int lane = t & 31;
    const int w = t >> 5;
    const int half = blockIdx.x >> 6;
    const int ibase = (blockIdx.x & 63) * 128;
    const int jbase0 = half * 4096;

    const uint32_t sbase = smem_u32(dsmem);
    const uint32_t abase = (sbase + 127) & ~127u;
    char* ab = dsmem + (abase - sbase);

    // stage e2 (prescaled by log2e): all 512 threads
    {
        float4* dst = reinterpret_cast<float4*>(ab + E2S_OFF);
        const float4* src = reinterpret_cast<const float4*>(g_e2 + jbase0);
        #pragma unroll
        for (int q = 0; q < 2; q++) {
            float4 v = src[t + q * 512];
            v.x *= LOG2E; v.y *= LOG2E; v.z *= LOG2E; v.w *= LOG2E;
            dst[t + q * 512] = v;
        }
    }
    const float* e2s = reinterpret_cast<const float*>(ab + E2S_OFF);

    // ================= producer state (warps 0-7, t < 256) =================
    const int prow = t >> 1;            // row within block (0..127)
    const int pseg = t & 1;             // j segment (0 or 1) * 32
    const int jloc0 = pseg * 32;
    const float ei = g_e1[ibase + prow] * LOG2E;

    const uint4* mrow_p = reinterpret_cast<const uint4*>(
        mask + (size_t)(ibase + prow) * N_NODES + jbase0 + jloc0);
    const int hd0 = t >> 3;             // 0..31
    const int hj0 = t & 7;
    const __nv_bfloat16* bh0p = g_ht_hi + (size_t)hd0 * N_NODES + jbase0 + hj0 * 8;
    const __nv_bfloat16* bh1p = bh0p + (size_t)32 * N_NODES;
    const __nv_bfloat16* bl0p = g_ht_lo + (size_t)hd0 * N_NODES + jbase0 + hj0 * 8;
    const __nv_bfloat16* bl1p = bl0p + (size_t)32 * N_NODES;

    uint4 mreg[8];
    uint4 hh0, hh1, hl0, hl1;
    unsigned long long zacc = 0ull;

    // ================= consumer state (warps 8-15) =================
    const int wc = w - 8;
    const int mrow = (wc & 3) * 32;
    const int nc0 = (wc >> 2) * 32;
    const uint32_t a_base0 = (uint32_t)((mrow + (lane & 15)) * PROW + ((lane >> 4) << 4));
    const uint32_t a_base1 = a_base0 + 16 * PROW;
    const uint32_t b_row = (uint32_t)(((lane >> 4) << 3) + (lane & 7));
    const uint32_t b_byt = (uint32_t)(((lane >> 3) & 1) << 4);
    const uint32_t b_base0 = (uint32_t)((nc0 + b_row) * PROW + b_byt);
    const uint32_t b_base1 = (uint32_t)((nc0 + 16 + b_row) * PROW + b_byt);

    float acc[2][4][4];
    #pragma unroll
    for (int mf = 0; mf < 2; mf++)
        #pragma unroll
        for (int nf = 0; nf < 4; nf++)
            #pragma unroll
            for (int c = 0; c < 4; c++) acc[mf][nf][c] = 0.f;

    // prologue prefetch (producers, tile 0)
    if (w < 8) {
        #pragma unroll
        for (int g = 0; g < 8; g++) mreg[g] = mrow_p[g];
        hh0 = *reinterpret_cast<const uint4*>(bh0p);
        hh1 = *reinterpret_cast<const uint4*>(bh1p);
        hl0 = *reinterpret_cast<const uint4*>(bl0p);
        hl1 = *reinterpret_cast<const uint4*>(bl1p);
    }

    for (int it = 0; it <= NT_HALF; it++) {
        __syncthreads();
        if (w < 8) {
            if (it < NT_HALF) {
                const int buf = it & 1;
                // stage H tile
                {
                    const uint32_t so1 = (uint32_t)(hd0 * PROW + hj0 * 16);
                    const uint32_t so2 = so1 + 32 * PROW;
                    *reinterpret_cast<uint4*>(ab + BHI_OFF(buf) + so1) = hh0;
                    *reinterpret_cast<uint4*>(ab + BHI_OFF(buf) + so2) = hh1;
                    *reinterpret_cast<uint4*>(ab + BLO_OFF(buf) + so1) = hl0;
                    *reinterpret_cast<uint4*>(ab + BLO_OFF(buf) + so2) = hl1;
                }
                // compute P: 32 elems, 4 groups of 8
                {
                    const float* e2p = e2s + it * 64 + jloc0;
                    const uint32_t ro = (uint32_t)(prow * PROW + jloc0 * 2);
                    #pragma unroll
                    for (int g = 0; g < 4; g++) {
                        const float4 ea = reinterpret_cast<const float4*>(e2p)[2 * g];
                        const float4 eb = reinterpret_cast<const float4*>(e2p)[2 * g + 1];
                        const float e2a[8] = {ea.x, ea.y, ea.z, ea.w,
                                              eb.x, eb.y, eb.z, eb.w};
                        const uint4 ma = mreg[2 * g];
                        const uint4 mb = mreg[2 * g + 1];
                        const uint32_t mm[8] = {ma.x, ma.y, ma.z, ma.w,
                                                mb.x, mb.y, mb.z, mb.w};
                        uint32_t hiu[4], lou[4];
                        #pragma unroll
                        for (int kk = 0; kk < 4; kk++) {
                            float s0 = ei + e2a[2 * kk];
                            float s1 = ei + e2a[2 * kk + 1];
                            s0 = fmaxf(s0, 0.2f * s0);
                            s1 = fmaxf(s1, 0.2f * s1);
                            float p0 = ex2(s0);
                            float p1 = ex2(s1);
                            p0 = __uint_as_float(__float_as_uint(p0) &
                                                 (uint32_t)(-(int)mm[2 * kk]));
                            p1 = __uint_as_float(__float_as_uint(p1) &
                                                 (uint32_t)(-(int)mm[2 * kk + 1]));
                            add2(zacc, pk2(p0, p1));
                            const uint32_t uh = pack_bf16x2(p0, p1);
                            const float f0 = __uint_as_float(uh << 16);
                            const float f1 = __uint_as_float(uh & 0xffff0000u);
                            hiu[kk] = uh;
                            lou[kk] = pack_bf16x2(p0 - f0, p1 - f1);
                        }
                        *reinterpret_cast<uint4*>(ab + PHI_OFF(buf) + ro + g * 16) =
                            make_uint4(hiu[0], hiu[1], hiu[2], hiu[3]);
                        *reinterpret_cast<uint4*>(ab + PLO_OFF(buf) + ro + g * 16) =
                            make_uint4(lou[0], lou[1], lou[2], lou[3]);
                    }
                }
                // prefetch next tile (wrap keeps addresses valid)
                {
                    const int nt = (it + 1 < NT_HALF) ? it + 1 : 0;
                    const uint4* mp = mrow_p + nt * 16;
                    #pragma unroll
                    for (int g = 0; g < 8; g++) mreg[g] = mp[g];
                    hh0 = *reinterpret_cast<const uint4*>(bh0p + nt * 64);
                    hh1 = *reinterpret_cast<const uint4*>(bh1p + nt * 64);
                    hl0 = *reinterpret_cast<const uint4*>(bl0p + nt * 64);
                    hl1 = *reinterpret_cast<const uint4*>(bl1p + nt * 64);
                }
            }
        } else {
            if (it >= 1) {
                const int buf = (it - 1) & 1;
                const uint32_t phi = abase + PHI_OFF(buf);
                const uint32_t plo = abase + PLO_OFF(buf);
                const uint32_t bhi = abase + BHI_OFF(buf);
                const uint32_t blo = abase + BLO_OFF(buf);
                #pragma unroll
                for (int kk = 0; kk < 4; kk++) {
                    const uint32_t off = (uint32_t)(kk * 32);
                    uint32_t ah0[4], ah1[4], al0[4], al1[4];
                    uint32_t bh0[4], bh1[4], bl0[4], bl1[4];
                    ldsm_x4(ah0, phi + a_base0 + off);
                    ldsm_x4(ah1, phi + a_base1 + off);
                    ldsm_x4(al0, plo + a_base0 + off);
                    ldsm_x4(al1, plo + a_base1 + off);
                    ldsm_x4(bh0, bhi + b_base0 + off);
                    ldsm_x4(bh1, bhi + b_base1 + off);
                    ldsm_x4(bl0, blo + b_base0 + off);
                    ldsm_x4(bl1, blo + b_base1 + off);
                    // hi * hi
                    mma16816(acc[0][0], ah0, &bh0[0]);
                    mma16816(acc[0][1], ah0, &bh0[2]);
                    mma16816(acc[0][2], ah0, &bh1[0]);
                    mma16816(acc[0][3], ah0, &bh1[2]);
                    mma16816(acc[1][0], ah1, &bh0[0]);
                    mma16816(acc[1][1], ah1, &bh0[2]);
                    mma16816(acc[1][2], ah1, &bh1[0]);
                    mma16816(acc[1][3], ah1, &bh1[2]);
                    // lo * hi
                    mma16816(acc[0][0], al0, &bh0[0]);
                    mma16816(acc[0][1], al0, &bh0[2]);
                    mma16816(acc[0][2], al0, &bh1[0]);
                    mma16816(acc[0][3], al0, &bh1[2]);
                    mma16816(acc[1][0], al1, &bh0[0]);
                    mma16816(acc[1][1], al1, &bh0[2]);
                    mma16816(acc[1][2], al1, &bh1[0]);
                    mma16816(acc[1][3], al1, &bh1[2]);
                    // hi * lo
                    mma16816(acc[0][0], ah0, &bl0[0]);
                    mma16816(acc[0][1], ah0, &bl0[2]);
                    mma16816(acc[0][2], ah0, &bl1[0]);
                    mma16816(acc[0][3], ah0, &bl1[2]);
                    mma16816(acc[1][0], ah1, &bl0[0]);
                    mma16816(acc[1][1], ah1, &bl0[2]);
                    mma16816(acc[1][2], ah1, &bl1[0]);
                    mma16816(acc[1][3], ah1, &bl1[2]);
                }
            }
        }
    }

    // ---- epilogue ----
    if (w < 8) {
        float zlo, zhi;
        upk2(zlo, zhi, zacc);
        float zsum = zlo + zhi;
        zsum += __shfl_xor_sync(0xffffffffu, zsum, 1);
        if ((t & 1) == 0) zs[prow] = zsum;
    } else {
        float* po = g_po + (size_t)half * (N_NODES * D_OUT);
        #pragma unroll
        for (int mf = 0; mf < 2; mf++) {
            const int r0 = ibase + mrow + mf * 16 + (lane >> 2);
            #pragma unroll
            for (int nf = 0; nf < 4; nf++) {
                const int col = nc0 + nf * 8 + (lane & 3) * 2;
                *reinterpret_cast<float2*>(po + (size_t)r0 * D_OUT + col) =
                    make_float2(acc[mf][nf][0], acc[mf][nf][1]);
                *reinterpret_cast<float2*>(po + (size_t)(r0 + 8) * D_OUT + col) =
                    make_float2(acc[mf][nf][2], acc[mf][nf][3]);
            }
        }
    }
    __syncthreads();
    if (t < 128) g_pz[half * N_NODES + ibase + t] = zs[t];
}

// ---------------- kernel 4: combine the two j-halves ----------------
__global__ void k_combine(float* __restrict__ out) {
    const int idx = blockIdx.x * 256 + threadIdx.x;
    const int i = idx >> 4;
    const float4 a = reinterpret_cast<const float4*>(g_po)[idx];
    const float4 b = reinterpret_cast<const float4*>(g_po)[idx + (N_NODES * D_OUT / 4)];
    const float rz = 1.0f / (g_pz[i] + g_pz[N_NODES + i]);
    float4 o;
    o.x = (a.x + b.x) * rz;
    o.y = (a.y + b.y) * rz;
    o.z = (a.z + b.z) * rz;
    o.w = (a.w + b.w) * rz;
    reinterpret_cast<float4*>(out)[idx] = o;
}

// ---------------- launch ----------------
extern "C" void kernel_launch(void* const* d_in, const int* in_sizes, int n_in,
                              void* d_out, int out_size) {
    const float* x     = (const float*)d_in[0];   // [8192, 256]
    const int*   mask  = (const int*)d_in[1];     // [8192, 8192]
    const float* trans = (const float*)d_in[2];   // [256, 64]
    const float* attn  = (const float*)d_in[3];   // [128, 1]
    float* out = (float*)d_out;                   // [8192, 64]

    cudaFuncSetAttribute(k_attn_ws, cudaFuncAttributeMaxDynamicSharedMemorySize,
                         SMEM_BYTES);

    k_h_gemm<<<N_NODES / 16, 256>>>(x, trans);
    k_e<<<N_NODES / 8, 256>>>(attn);
    k_attn_ws<<<128, 512, SMEM_BYTES>>>(mask);
    k_combine<<<(N_NODES * D_OUT / 4) / 256, 256>>>(out);
}